// round 6
// baseline (speedup 1.0000x reference)
#include <cuda_runtime.h>

// out[h1,w1,c1,h2,w2,c2] = g^(|dh|+|dw|+|dc|) * (1 + spec_pe[c1,c2]*mean[h1,w1,c1]) * decay[c1]
// mean[h1,w1,c1] = Sh[h1]*Sw[w1]*Sc[c1] / (H*W*C), separable geometric sums.
// H=W=32, C=8. Output: 1024 * 65536 floats = 268.4 MB, pure write-bound.
//
// R6 change vs R4 (best, ncu 41.66us): single-wave grid. 1024 CTAs at 6 CTAs/SM
// = wave of 888 + tail wave of 136 (chip 85% idle during tail). Now grid=512,
// each CTA does 2 (h1,w1) tiles -> one full wave, no tail. Store path = R4.

#define GAMMA 0.9f

__global__ __launch_bounds__(256) void mrp3d_kernel(const float* __restrict__ decay,
                                                    const float* __restrict__ spec_pe,
                                                    float* __restrict__ out) {
    __shared__ float sPow[40];        // gamma^d, d = 0..39 (max needed: 31)
    __shared__ float4 sCoef[2][16];   // per-tile fused coef [c1][c2-half]

    const int t = threadIdx.x;

    // Build gamma^d table (iterative product; few-ulp error, fine for 1e-3 tol)
    if (t < 40) {
        float p = 1.0f;
        for (int i = 0; i < t; ++i) p *= GAMMA;
        sPow[t] = p;
    }
    __syncthreads();

    // Build fused 8x8 coefficient tables for BOTH tiles of this CTA.
    // threads 0..127: tileIdx = t>>6, c1 = (t>>3)&7, c2 = t&7
    if (t < 128) {
        const int tileIdx = t >> 6;
        const int tile    = blockIdx.x * 2 + tileIdx;
        const int h1 = tile >> 5;
        const int w1 = tile & 31;
        const int c1 = (t >> 3) & 7;
        const int c2 = t & 7;
        float Sh = 0.0f, Sw = 0.0f, Sc = 0.0f;
        #pragma unroll
        for (int j = 0; j < 32; ++j) {
            Sh += sPow[abs(h1 - j)];
            Sw += sPow[abs(w1 - j)];
        }
        #pragma unroll
        for (int j = 0; j < 8; ++j) Sc += sPow[abs(c1 - j)];
        const float mean = Sh * Sw * Sc * (1.0f / 8192.0f);
        const float coef = decay[c1] * (1.0f + spec_pe[c1 * 8 + c2] * mean) * sPow[abs(c1 - c2)];
        reinterpret_cast<float*>(sCoef[tileIdx])[t & 63] = coef;
    }
    __syncthreads();

    // Store path identical to R4 best, looped over the 2 tiles.
    const int half   = t & 1;
    const int w2     = (t >> 1) & 31;
    const int h2base = t >> 6;

    #pragma unroll
    for (int tileIdx = 0; tileIdx < 2; ++tileIdx) {
        const int tile = blockIdx.x * 2 + tileIdx;
        const int h1 = tile >> 5;
        const int w1 = tile & 31;
        const float sW = sPow[abs(w1 - w2)];
        float4* __restrict__ outv = reinterpret_cast<float4*>(out) + (size_t)tile * 16384;

        #pragma unroll
        for (int c1 = 0; c1 < 8; ++c1) {
            const float4 cf = sCoef[tileIdx][(c1 << 1) | half];
            float4* outc = outv + c1 * 2048;
            #pragma unroll
            for (int it = 0; it < 8; ++it) {
                const int h2 = h2base + (it << 2);
                const int r  = t + (it << 8);
                const float s = sPow[abs(h1 - h2)] * sW;
                float4 o;
                o.x = s * cf.x;
                o.y = s * cf.y;
                o.z = s * cf.z;
                o.w = s * cf.w;
                outc[r] = o;
            }
        }
    }
}

extern "C" void kernel_launch(void* const* d_in, const int* in_sizes, int n_in,
                              void* d_out, int out_size) {
    // Inputs: x (unused, 524288 elems), decay (8), spec_pe (64) — identify by size.
    const float* decay   = nullptr;
    const float* spec_pe = nullptr;
    for (int i = 0; i < n_in; ++i) {
        if (in_sizes[i] == 8)       decay   = (const float*)d_in[i];
        else if (in_sizes[i] == 64) spec_pe = (const float*)d_in[i];
    }
    mrp3d_kernel<<<512, 256>>>(decay, spec_pe, (float*)d_out);
}

// round 7
// speedup vs baseline: 1.0770x; 1.0770x over previous
#include <cuda_runtime.h>

// out[h1,w1,c1,h2,w2,c2] = g^(|dh|+|dw|+|dc|) * (1 + spec_pe[c1,c2]*mean[h1,w1,c1]) * decay[c1]
// mean[h1,w1,c1] = Sh[h1]*Sw[w1]*Sc[c1] / (H*W*C), separable geometric sums.
// H=W=32, C=8. Output: 1024 * 65536 floats = 268.4 MB, pure write-bound.
//
// R7 = R4 (verified best: ncu 41.66us) with the per-CTA serial gamma^d power
// chain replaced by a compile-time __constant__ table, parallel-copied into
// shared. Store path untouched. (R2/R3/R5/R6 knobs all proven neutral/negative;
// kernel is pinned at ~6.3-6.4 TB/s effective HBM write drain.)

#define GAMMA 0.9f

// gamma^d for d = 0..31 (max |delta| on any axis is 31)
__device__ __constant__ float cPow[32] = {
    1.0f,                  0.9f,                  0.81f,                 0.729f,
    0.6561f,               0.59049f,              0.531441f,             0.4782969f,
    0.43046721f,           0.387420489f,          0.3486784401f,         0.31381059609f,
    0.282429536481f,       0.2541865828329f,      0.22876792454961f,     0.205891132094649f,
    0.1853020188851841f,   0.166771816996666f,    0.150094635296999f,    0.135085171767299f,
    0.121576654590569f,    0.109418989131512f,    0.0984770902183612f,   0.0886293811965251f,
    0.0797664430768726f,   0.0717897987691853f,   0.0646108188922668f,   0.0581497370030401f,
    0.0523347633027361f,   0.0471012869724625f,   0.0423911582752162f,   0.0381520424476946f
};

__global__ __launch_bounds__(256) void mrp3d_kernel(const float* __restrict__ decay,
                                                    const float* __restrict__ spec_pe,
                                                    float* __restrict__ out) {
    __shared__ float sPow[32];    // gamma^d copied from constant
    __shared__ float4 sCoef[16];  // fused coef [c1][c2-half]: decay*(1+spec*mean)*g^|c1-c2|

    const int h1 = blockIdx.x >> 5;
    const int w1 = blockIdx.x & 31;
    const int t  = threadIdx.x;

    if (t < 32) sPow[t] = cPow[t];   // parallel copy, no serial chain
    __syncthreads();

    // Build fused 8x8 coefficient table for this (h1,w1)
    if (t < 64) {
        const int c1 = t >> 3;
        const int c2 = t & 7;
        float Sh = 0.0f, Sw = 0.0f, Sc = 0.0f;
        #pragma unroll
        for (int j = 0; j < 32; ++j) {
            Sh += sPow[abs(h1 - j)];
            Sw += sPow[abs(w1 - j)];
        }
        #pragma unroll
        for (int j = 0; j < 8; ++j) Sc += sPow[abs(c1 - j)];
        const float mean = Sh * Sw * Sc * (1.0f / 8192.0f);
        const float coef = decay[c1] * (1.0f + spec_pe[c1 * 8 + c2] * mean) * sPow[abs(c1 - c2)];
        reinterpret_cast<float*>(sCoef)[t] = coef;
    }
    __syncthreads();

    // Output slice for this (h1,w1): 65536 floats = 16384 float4, contiguous.
    float4* __restrict__ outv = reinterpret_cast<float4*>(out) + (size_t)blockIdx.x * 16384;

    // float4 index within c1-slice: r = (h2*32 + w2)*2 + half, r in [0,2048)
    // half = t&1, w2 = (t>>1)&31, h2 = (t>>6) + 4*it.
    const int half    = t & 1;
    const int w2      = (t >> 1) & 31;
    const int h2base  = t >> 6;
    const float sW    = sPow[abs(w1 - w2)];

    #pragma unroll
    for (int c1 = 0; c1 < 8; ++c1) {
        const float4 cf = sCoef[(c1 << 1) | half];
        float4* outc = outv + c1 * 2048;
        #pragma unroll
        for (int it = 0; it < 8; ++it) {
            const int h2 = h2base + (it << 2);
            const int r  = t + (it << 8);
            const float s = sPow[abs(h1 - h2)] * sW;
            float4 o;
            o.x = s * cf.x;
            o.y = s * cf.y;
            o.z = s * cf.z;
            o.w = s * cf.w;
            outc[r] = o;
        }
    }
}

extern "C" void kernel_launch(void* const* d_in, const int* in_sizes, int n_in,
                              void* d_out, int out_size) {
    // Inputs: x (unused, 524288 elems), decay (8), spec_pe (64) — identify by size.
    const float* decay   = nullptr;
    const float* spec_pe = nullptr;
    for (int i = 0; i < n_in; ++i) {
        if (in_sizes[i] == 8)       decay   = (const float*)d_in[i];
        else if (in_sizes[i] == 64) spec_pe = (const float*)d_in[i];
    }
    mrp3d_kernel<<<1024, 256>>>(decay, spec_pe, (float*)d_out);
}

// round 8
// speedup vs baseline: 1.0830x; 1.0056x over previous
#include <cuda_runtime.h>

// out[h1,w1,c1,h2,w2,c2] = g^(|dh|+|dw|+|dc|) * (1 + spec_pe[c1,c2]*mean[h1,w1,c1]) * decay[c1]
// mean[h1,w1,c1] = Sh[h1]*Sw[w1]*Sc[c1] / (H*W*C), separable geometric sums.
// H=W=32, C=8. Output: 1024 * 65536 floats = 268.4 MB, pure write-bound.
//
// FINAL (R8 = R4 = R1, verified fastest: bench 45.15us / ncu 41.66us).
// Knob sweep R2-R7 (L2 policy, occupancy, STG.256, wave shape, setup cost)
// all neutral or negative: kernel is pinned at ~6.4 TB/s effective HBM write
// drain, ~94% of the practical pure-write ceiling. Bytes written (268.4 MB
// fp32) are irreducible, so this is the roofline optimum.

#define GAMMA 0.9f

__global__ __launch_bounds__(256) void mrp3d_kernel(const float* __restrict__ decay,
                                                    const float* __restrict__ spec_pe,
                                                    float* __restrict__ out) {
    __shared__ float sPow[40];    // gamma^d, d = 0..39 (max needed: 31)
    __shared__ float4 sCoef[16];  // fused coef [c1][c2-half]: decay*(1+spec*mean)*g^|c1-c2|

    const int h1 = blockIdx.x >> 5;
    const int w1 = blockIdx.x & 31;
    const int t  = threadIdx.x;

    // Build gamma^d table (iterative product; few-ulp error, fine for 1e-3 tol)
    if (t < 40) {
        float p = 1.0f;
        for (int i = 0; i < t; ++i) p *= GAMMA;
        sPow[t] = p;
    }
    __syncthreads();

    // Build fused 8x8 coefficient table for this (h1,w1)
    if (t < 64) {
        const int c1 = t >> 3;
        const int c2 = t & 7;
        float Sh = 0.0f, Sw = 0.0f, Sc = 0.0f;
        #pragma unroll
        for (int j = 0; j < 32; ++j) {
            Sh += sPow[abs(h1 - j)];
            Sw += sPow[abs(w1 - j)];
        }
        #pragma unroll
        for (int j = 0; j < 8; ++j) Sc += sPow[abs(c1 - j)];
        const float mean = Sh * Sw * Sc * (1.0f / 8192.0f);
        const float coef = decay[c1] * (1.0f + spec_pe[c1 * 8 + c2] * mean) * sPow[abs(c1 - c2)];
        reinterpret_cast<float*>(sCoef)[t] = coef;
    }
    __syncthreads();

    // Output slice for this (h1,w1): 65536 floats = 16384 float4, contiguous.
    float4* __restrict__ outv = reinterpret_cast<float4*>(out) + (size_t)blockIdx.x * 16384;

    // float4 index within c1-slice: r = (h2*32 + w2)*2 + half, r in [0,2048)
    // half = t&1, w2 = (t>>1)&31, h2 = (t>>6) + 4*it.
    const int half    = t & 1;
    const int w2      = (t >> 1) & 31;
    const int h2base  = t >> 6;
    const float sW    = sPow[abs(w1 - w2)];

    #pragma unroll
    for (int c1 = 0; c1 < 8; ++c1) {
        const float4 cf = sCoef[(c1 << 1) | half];
        float4* outc = outv + c1 * 2048;
        #pragma unroll
        for (int it = 0; it < 8; ++it) {
            const int h2 = h2base + (it << 2);
            const int r  = t + (it << 8);
            const float s = sPow[abs(h1 - h2)] * sW;
            float4 o;
            o.x = s * cf.x;
            o.y = s * cf.y;
            o.z = s * cf.z;
            o.w = s * cf.w;
            outc[r] = o;
        }
    }
}

extern "C" void kernel_launch(void* const* d_in, const int* in_sizes, int n_in,
                              void* d_out, int out_size) {
    // Inputs: x (unused, 524288 elems), decay (8), spec_pe (64) — identify by size.
    const float* decay   = nullptr;
    const float* spec_pe = nullptr;
    for (int i = 0; i < n_in; ++i) {
        if (in_sizes[i] == 8)       decay   = (const float*)d_in[i];
        else if (in_sizes[i] == 64) spec_pe = (const float*)d_in[i];
    }
    mrp3d_kernel<<<1024, 256>>>(decay, spec_pe, (float*)d_out);
}

// round 9
// speedup vs baseline: 1.1125x; 1.0272x over previous
#include <cuda_runtime.h>

// out[h1,w1,c1,h2,w2,c2] = g^(|dh|+|dw|+|dc|) * (1 + spec_pe[c1,c2]*mean[h1,w1,c1]) * decay[c1]
// mean[h1,w1,c1] = Sh[h1]*Sw[w1]*Sc[c1] / (H*W*C), separable geometric sums.
// H=W=32, C=8. Output: 1024 * 65536 floats = 268.4 MB, pure write-bound.
//
// R9: same algorithm/store path as R4 (verified best) but 512-thread CTAs.
// Same resident warps/SM (3x512 = 6x256 = 48), but half the barrier groups
// and half the number of concurrent DRAM write streams (444 x 512KB instead
// of 888 x 256KB) -> coarser per-stream page locality in the non-saturated
// write-turnaround regime. Last untested configuration axis.

#define GAMMA 0.9f

__global__ __launch_bounds__(512) void mrp3d_kernel(const float* __restrict__ decay,
                                                    const float* __restrict__ spec_pe,
                                                    float* __restrict__ out) {
    __shared__ float sPow[40];    // gamma^d, d = 0..39 (max needed: 31)
    __shared__ float4 sCoef[16];  // fused coef [c1][c2-half]: decay*(1+spec*mean)*g^|c1-c2|

    const int h1 = blockIdx.x >> 5;
    const int w1 = blockIdx.x & 31;
    const int t  = threadIdx.x;

    // Build gamma^d table (iterative product; few-ulp error, fine for 1e-3 tol)
    if (t < 40) {
        float p = 1.0f;
        for (int i = 0; i < t; ++i) p *= GAMMA;
        sPow[t] = p;
    }
    __syncthreads();

    // Build fused 8x8 coefficient table for this (h1,w1)
    if (t < 64) {
        const int c1 = t >> 3;
        const int c2 = t & 7;
        float Sh = 0.0f, Sw = 0.0f, Sc = 0.0f;
        #pragma unroll
        for (int j = 0; j < 32; ++j) {
            Sh += sPow[abs(h1 - j)];
            Sw += sPow[abs(w1 - j)];
        }
        #pragma unroll
        for (int j = 0; j < 8; ++j) Sc += sPow[abs(c1 - j)];
        const float mean = Sh * Sw * Sc * (1.0f / 8192.0f);
        const float coef = decay[c1] * (1.0f + spec_pe[c1 * 8 + c2] * mean) * sPow[abs(c1 - c2)];
        reinterpret_cast<float*>(sCoef)[t] = coef;
    }
    __syncthreads();

    // Output slice for this (h1,w1): 65536 floats = 16384 float4, contiguous.
    float4* __restrict__ outv = reinterpret_cast<float4*>(out) + (size_t)blockIdx.x * 16384;

    // float4 index within c1-slice: r = (h2*32 + w2)*2 + half, r in [0,2048)
    // For 512 threads: half = t&1, w2 = (t>>1)&31, h2base = t>>6 (0..7),
    // h2 = h2base + 8*it, it in [0,4); r = t + 512*it.
    const int half    = t & 1;
    const int w2      = (t >> 1) & 31;
    const int h2base  = t >> 6;
    const float sW    = sPow[abs(w1 - w2)];

    #pragma unroll
    for (int c1 = 0; c1 < 8; ++c1) {
        const float4 cf = sCoef[(c1 << 1) | half];
        float4* outc = outv + c1 * 2048;
        #pragma unroll
        for (int it = 0; it < 4; ++it) {
            const int h2 = h2base + (it << 3);
            const int r  = t + (it << 9);
            const float s = sPow[abs(h1 - h2)] * sW;
            float4 o;
            o.x = s * cf.x;
            o.y = s * cf.y;
            o.z = s * cf.z;
            o.w = s * cf.w;
            outc[r] = o;
        }
    }
}

extern "C" void kernel_launch(void* const* d_in, const int* in_sizes, int n_in,
                              void* d_out, int out_size) {
    // Inputs: x (unused, 524288 elems), decay (8), spec_pe (64) — identify by size.
    const float* decay   = nullptr;
    const float* spec_pe = nullptr;
    for (int i = 0; i < n_in; ++i) {
        if (in_sizes[i] == 8)       decay   = (const float*)d_in[i];
        else if (in_sizes[i] == 64) spec_pe = (const float*)d_in[i];
    }
    mrp3d_kernel<<<1024, 512>>>(decay, spec_pe, (float*)d_out);
}